// round 8
// baseline (speedup 1.0000x reference)
#include <cuda_runtime.h>
#include <cuda_bf16.h>
#include <math.h>
#include <stdint.h>

#define S_LEN 4096
#define HID 2048
#define NH 16
#define NKV 4
#define DH 128
#define BLK 64
#define MSK 32
#define KTOP 8
#define NBLK 64   // S_LEN / BLK
#define QKV_W 3072  // 2048 q + 512 k + 512 v

typedef __nv_bfloat16 bf16;
typedef unsigned long long u64t;

// ---------------- scratch ----------------
__device__ float g_qkv[S_LEN * QKV_W];      // fused QKV output (q:0, k:2048, v:2560)
__device__ float g_sq[NH * NBLK * MSK];
__device__ float g_sk[NKV * NBLK * MSK];
__device__ int   g_idx[NH * NBLK * KTOP];
__device__ float2 g_cs[S_LEN * 64];

__device__ bf16 g_ahi[S_LEN * HID];
__device__ bf16 g_alo[S_LEN * HID];
__device__ bf16 g_bhi[S_LEN * HID];   // attention out hi
__device__ bf16 g_blo[S_LEN * HID];   // attention out lo
__device__ bf16 g_wqkv_h[QKV_W * HID];
__device__ bf16 g_wqkv_l[QKV_W * HID];
__device__ bf16 g_wot_h[HID * HID];
__device__ bf16 g_wot_l[HID * HID];

// ================= helpers =================
__device__ __forceinline__ uint32_t smem_u32(const void* p) {
    uint32_t a;
    asm("{ .reg .u64 t; cvta.to.shared.u64 t, %1; cvt.u32.u64 %0, t; }" : "=r"(a) : "l"(p));
    return a;
}
#define CP_ASYNC16(sa, ga) \
    asm volatile("cp.async.cg.shared.global [%0], [%1], 16;" :: "r"(sa), "l"(ga))
#define CP_COMMIT() asm volatile("cp.async.commit_group;")
#define CP_WAIT(n)  asm volatile("cp.async.wait_group %0;" :: "n"(n))
#define LDSM4(R, A) \
    asm volatile("ldmatrix.sync.aligned.m8n8.x4.shared.b16 {%0,%1,%2,%3}, [%4];" \
                 : "=r"((R)[0]), "=r"((R)[1]), "=r"((R)[2]), "=r"((R)[3]) : "r"(A))
#define MMA16816(D, A, B0, B1) \
    asm volatile("mma.sync.aligned.m16n8k16.row.col.f32.bf16.bf16.f32 " \
                 "{%0,%1,%2,%3}, {%4,%5,%6,%7}, {%8,%9}, {%0,%1,%2,%3};" \
                 : "+f"((D)[0]), "+f"((D)[1]), "+f"((D)[2]), "+f"((D)[3]) \
                 : "r"((A)[0]), "r"((A)[1]), "r"((A)[2]), "r"((A)[3]), "r"(B0), "r"(B1))

// Blackwell packed fp32x2 math
#define FMA2(d, a, b) asm("fma.rn.f32x2 %0, %1, %2, %0;" : "+l"(d) : "l"(a), "l"(b))
#define MUL2(d, a, b) asm("mul.rn.f32x2 %0, %1, %2;" : "=l"(d) : "l"(a), "l"(b))
__device__ __forceinline__ u64t bcast2(float x) {
    u64t r; asm("mov.b64 %0, {%1, %1};" : "=l"(r) : "f"(x)); return r;
}
__device__ __forceinline__ float hsum2(u64t v) {
    float lo, hi; asm("mov.b64 {%0, %1}, %2;" : "=f"(lo), "=f"(hi) : "l"(v));
    return lo + hi;
}
__device__ __forceinline__ void unpack2(u64t v, float& lo, float& hi) {
    asm("mov.b64 {%0, %1}, %2;" : "=f"(lo), "=f"(hi) : "l"(v));
}

// ================= HMMA GEMM: C[M,N] = A[M,K] * Bt[N,K]^T (3-pass hi/lo) =================
#define GH_STRIDE_B 80
#define GH_ARR (128 * GH_STRIDE_B)
#define GH_STAGE (4 * GH_ARR)
#define GH_STAGES 4
#define GH_SMEM (GH_STAGES * GH_STAGE)

__global__ __launch_bounds__(256) void gemm_hmma(const bf16* __restrict__ Ahi,
                                                 const bf16* __restrict__ Alo,
                                                 const bf16* __restrict__ Bhi,
                                                 const bf16* __restrict__ Blo,
                                                 float* __restrict__ C,
                                                 int M, int N, int K) {
    extern __shared__ char smembuf[];
    const uint32_t sbase = smem_u32(smembuf);
    const int t = threadIdx.x;
    const int L = t & 31, wid = t >> 5;
    const int wm = wid >> 2, wn = wid & 3;
    const int bm = blockIdx.y * 128, bn = blockIdx.x * 128;
    const int NC = K >> 5;

    float acc[16][4];
#pragma unroll
    for (int i = 0; i < 16; i++)
#pragma unroll
        for (int j = 0; j < 4; j++) acc[i][j] = 0.f;

#define GH_LOAD(cc, s) do {                                                   \
        int kc_ = (cc) << 5;                                                  \
        uint32_t st_ = sbase + (s) * GH_STAGE;                                \
        _Pragma("unroll")                                                     \
        for (int i_ = 0; i_ < 2; i_++) {                                      \
            int idx_ = t + i_ * 256;                                          \
            int r_ = idx_ >> 2, ch_ = idx_ & 3;                               \
            uint32_t sw_ = r_ * GH_STRIDE_B + ch_ * 16;                       \
            size_t ga_ = (size_t)(bm + r_) * K + kc_ + ch_ * 8;               \
            size_t gb_ = (size_t)(bn + r_) * K + kc_ + ch_ * 8;               \
            CP_ASYNC16(st_ + sw_,              Ahi + ga_);                    \
            CP_ASYNC16(st_ + GH_ARR + sw_,     Alo + ga_);                    \
            CP_ASYNC16(st_ + 2 * GH_ARR + sw_, Bhi + gb_);                    \
            CP_ASYNC16(st_ + 3 * GH_ARR + sw_, Blo + gb_);                    \
        }                                                                     \
        CP_COMMIT();                                                          \
    } while (0)

    GH_LOAD(0, 0);
    GH_LOAD(1, 1);
    GH_LOAD(2, 2);

    const uint32_t a_lane = (uint32_t)((wm * 64 + (L & 7) + ((L >> 3) & 1) * 8) * GH_STRIDE_B
                                       + ((L >> 4) & 1) * 16);
    const uint32_t b_lane = (uint32_t)((wn * 32 + (L & 7) + ((L >> 4) & 1) * 8) * GH_STRIDE_B
                                       + ((L >> 3) & 1) * 16);

    for (int c = 0; c < NC; c++) {
        if (c + 3 < NC)      { CP_WAIT(2); }
        else if (c + 2 < NC) { CP_WAIT(2); }
        else if (c + 1 < NC) { CP_WAIT(1); }
        else                 { CP_WAIT(0); }
        __syncthreads();
        if (c + 3 < NC) GH_LOAD(c + 3, (c + 3) & 3);

        uint32_t st = sbase + (c & 3) * GH_STAGE;
#pragma unroll
        for (int ks = 0; ks < 2; ks++) {
            uint32_t kb = ks * 32;
            uint32_t ah[4][4], al[4][4], bh[2][4], bl[2][4];
#pragma unroll
            for (int mi = 0; mi < 4; mi++) {
                uint32_t ad = st + a_lane + mi * 16 * GH_STRIDE_B + kb;
                LDSM4(ah[mi], ad);
                LDSM4(al[mi], ad + GH_ARR);
            }
#pragma unroll
            for (int bi = 0; bi < 2; bi++) {
                uint32_t bd = st + 2 * GH_ARR + b_lane + bi * 16 * GH_STRIDE_B + kb;
                LDSM4(bh[bi], bd);
                LDSM4(bl[bi], bd + GH_ARR);
            }
#pragma unroll
            for (int mi = 0; mi < 4; mi++)
#pragma unroll
                for (int ni = 0; ni < 4; ni++) {
                    float* d = acc[mi * 4 + ni];
                    int bi = ni >> 1, sub = (ni & 1) * 2;
                    MMA16816(d, ah[mi], bh[bi][sub], bh[bi][sub + 1]);
                    MMA16816(d, ah[mi], bl[bi][sub], bl[bi][sub + 1]);
                    MMA16816(d, al[mi], bh[bi][sub], bh[bi][sub + 1]);
                }
        }
    }

#pragma unroll
    for (int mi = 0; mi < 4; mi++)
#pragma unroll
        for (int ni = 0; ni < 4; ni++) {
            float* d = acc[mi * 4 + ni];
            int row = bm + wm * 64 + mi * 16 + (L >> 2);
            int col = bn + wn * 32 + ni * 8 + (L & 3) * 2;
            *(float2*)(C + (size_t)row * N + col) = make_float2(d[0], d[1]);
            *(float2*)(C + (size_t)(row + 8) * N + col) = make_float2(d[2], d[3]);
        }
}

// ---------------- fp32 -> bf16 hi/lo split ----------------
__global__ void split_kernel(const float* __restrict__ x, bf16* __restrict__ hi,
                             bf16* __restrict__ lo, int n4) {
    int i = blockIdx.x * 256 + threadIdx.x;
    if (i >= n4) return;
    float4 v = ((const float4*)x)[i];
    float vv[4] = {v.x, v.y, v.z, v.w};
    bf16 h[4], l[4];
#pragma unroll
    for (int j = 0; j < 4; j++) {
        h[j] = __float2bfloat16(vv[j]);
        l[j] = __float2bfloat16(vv[j] - __bfloat162float(h[j]));
    }
    *(uint2*)(hi + 4 * (size_t)i) = *(uint2*)h;
    *(uint2*)(lo + 4 * (size_t)i) = *(uint2*)l;
}

// ---------------- fused QKV weight transpose + split: Bt[3072][2048] ----------------
__global__ void tsplit_qkv(const float* __restrict__ Wq, const float* __restrict__ Wk,
                           const float* __restrict__ Wv,
                           bf16* __restrict__ hi, bf16* __restrict__ lo) {
    __shared__ float tile[32][33];
    int nb = blockIdx.x * 32, kb = blockIdx.y * 32;
    int tx = threadIdx.x, ty = threadIdx.y;
    const float* W; int Nc, nc0;
    if (nb < 2048)      { W = Wq; Nc = 2048; nc0 = nb; }
    else if (nb < 2560) { W = Wk; Nc = 512;  nc0 = nb - 2048; }
    else                { W = Wv; Nc = 512;  nc0 = nb - 2560; }
#pragma unroll
    for (int i = 0; i < 32; i += 8)
        tile[ty + i][tx] = W[(size_t)(kb + ty + i) * Nc + nc0 + tx];
    __syncthreads();
#pragma unroll
    for (int i = 0; i < 32; i += 8) {
        float v = tile[tx][ty + i];
        size_t o = (size_t)(nb + ty + i) * HID + kb + tx;
        bf16 h = __float2bfloat16(v);
        hi[o] = h;
        lo[o] = __float2bfloat16(v - __bfloat162float(h));
    }
}

// ---------------- Wo transpose + split ----------------
__global__ void tsplit_kernel(const float* __restrict__ W, bf16* __restrict__ hi,
                              bf16* __restrict__ lo, int K, int N) {
    __shared__ float tile[32][33];
    int kb = blockIdx.y * 32, nb = blockIdx.x * 32;
    int tx = threadIdx.x, ty = threadIdx.y;
#pragma unroll
    for (int i = 0; i < 32; i += 8)
        tile[ty + i][tx] = W[(size_t)(kb + ty + i) * N + nb + tx];
    __syncthreads();
#pragma unroll
    for (int i = 0; i < 32; i += 8) {
        float v = tile[tx][ty + i];
        size_t o = (size_t)(nb + ty + i) * K + kb + tx;
        bf16 h = __float2bfloat16(v);
        hi[o] = h;
        lo[o] = __float2bfloat16(v - __bfloat162float(h));
    }
}

// ---------------- cos/sin table ----------------
__global__ void cs_kernel(const int* __restrict__ pos_ids) {
    int idx = blockIdx.x * 256 + threadIdx.x;
    if (idx >= S_LEN * 64) return;
    int s = idx >> 6, i = idx & 63;
    double inv = exp((double)i * -0.14391156831212753);
    double f = (double)pos_ids[s] * inv;
    const double TWO_PI = 6.283185307179586476925287;
    double fr = f - TWO_PI * floor(f * 0.15915494309189534561);
    g_cs[idx] = make_float2(cosf((float)fr), sinf((float)fr));
}

// ---------------- RoPE on fused QKV buffer ----------------
__global__ void rope_kernel(int coloff, int nheads) {
    int idx = blockIdx.x * 256 + threadIdx.x;
    int total = S_LEN * nheads * 64;
    if (idx >= total) return;
    int i = idx & 63;
    int h = (idx >> 6) % nheads;
    int s = idx / (64 * nheads);
    float2 cs = g_cs[s * 64 + i];
    float* p = g_qkv + (size_t)s * QKV_W + coloff + h * DH;
    float x1 = p[i], x2 = p[i + 64];
    p[i]      = x1 * cs.x - x2 * cs.y;
    p[i + 64] = x2 * cs.x + x1 * cs.y;
}

// ---------------- sketch ----------------
__global__ void sketch_kernel(int coloff, const float* __restrict__ H,
                              float* __restrict__ dst) {
    int blk = blockIdx.x, h = blockIdx.y;
    int t = threadIdx.x;  // 128
    __shared__ float xb[128];
    const float* base = g_qkv + (size_t)blk * BLK * QKV_W + coloff + h * DH + t;
    float s = 0.f;
    for (int r = 0; r < BLK; r++) s += base[(size_t)r * QKV_W];
    xb[t] = s * (1.f / 64.f);
    __syncthreads();
    if (t < MSK) {
        float a = 0.f;
        for (int d = 0; d < DH; d++) a += xb[d] * H[d * MSK + t];
        dst[((size_t)h * NBLK + blk) * MSK + t] = a;
    }
}

// ---------------- top-k ----------------
__global__ void topk_kernel() {
    int qb = blockIdx.x, h = blockIdx.y;
    int j = threadIdx.x;
    __shared__ float sc[64];
    float s;
    if (j > qb) {
        s = -1e9f;
    } else {
        const float* a = g_sq + ((size_t)h * NBLK + qb) * MSK;
        const float* b = g_sk + ((size_t)(h >> 2) * NBLK + j) * MSK;
        s = 0.f;
        for (int m = 0; m < MSK; m++) s += a[m] * b[m];
    }
    if (j == qb) s = 1e9f;
    sc[j] = s;
    __syncthreads();
    if (j == 0) {
        for (int tsel = 0; tsel < KTOP; tsel++) {
            float best = -3.4e38f;
            int bi = 0;
            for (int jj = 0; jj < 64; jj++)
                if (sc[jj] > best) { best = sc[jj]; bi = jj; }
            g_idx[((size_t)h * NBLK + qb) * KTOP + tsel] = bi;
            sc[bi] = -3.4e38f;
        }
    }
}

// ---------------- block-sparse flash attention (f32x2 math) ----------------
#define QS_STR 132
#define SC_STR 68
#define ATTN_SMEM ((64 * QS_STR * 2 + 64 * SC_STR + 192) * sizeof(float))

__global__ __launch_bounds__(256) void attn_kernel() {
    extern __shared__ float sm[];
    float* Qs  = sm;                     // 64 x 132
    float* KVs = Qs + 64 * QS_STR;       // 64 x 132
    float* SC  = KVs + 64 * QS_STR;      // 64 x 68
    float* Mx  = SC + 64 * SC_STR;
    float* Lw  = Mx + 64;
    float* Al  = Lw + 64;

    const int qb = blockIdx.x, h = blockIdx.y, kvh = h >> 2;
    const int t = threadIdx.x;
    const float scale = 0.08838834764831845f;

    // load Q block (fp32, row stride QKV_W)
#pragma unroll
    for (int i = 0; i < 8; i++) {
        int li = t + i * 256;
        int r = li >> 5, c = (li & 31) << 2;
        float4 a = *(const float4*)(g_qkv + (size_t)(qb * 64 + r) * QKV_W + h * DH + c);
        *(float4*)&Qs[r * QS_STR + c] = a;
    }
    if (t < 64) { Mx[t] = -3.4e38f; Lw[t] = 0.f; }

    const int q0 = (t >> 4) << 2;   // score/O tile: 4 query rows
    const int k0 = (t & 15) << 2;   // score tile: 4 key cols
    const int dc = (t & 15) << 3;   // O tile: 8 dims

    u64t o2[4][4];
#pragma unroll
    for (int i = 0; i < 4; i++)
#pragma unroll
        for (int j = 0; j < 4; j++) o2[i][j] = 0ULL;

    for (int it = 0; it < KTOP; it++) {
        int ki = g_idx[((size_t)h * NBLK + qb) * KTOP + it];
        __syncthreads();
        // load K block
#pragma unroll
        for (int i = 0; i < 8; i++) {
            int li = t + i * 256;
            int r = li >> 5, c = (li & 31) << 2;
            float4 a = *(const float4*)(g_qkv + (size_t)(ki * 64 + r) * QKV_W + 2048 + kvh * DH + c);
            *(float4*)&KVs[r * QS_STR + c] = a;
        }
        __syncthreads();

        // ---- scores: 4x4 tile, f32x2 paired over d (free pairing) ----
        u64t acc2[4][4];
#pragma unroll
        for (int i = 0; i < 4; i++)
#pragma unroll
            for (int j = 0; j < 4; j++) acc2[i][j] = 0ULL;
        for (int d4 = 0; d4 < 32; d4++) {
            ulonglong2 qv[4], kv[4];
#pragma unroll
            for (int i = 0; i < 4; i++) qv[i] = *(ulonglong2*)&Qs[(q0 + i) * QS_STR + d4 * 4];
#pragma unroll
            for (int j = 0; j < 4; j++) kv[j] = *(ulonglong2*)&KVs[(k0 + j) * QS_STR + d4 * 4];
#pragma unroll
            for (int i = 0; i < 4; i++)
#pragma unroll
                for (int j = 0; j < 4; j++) {
                    FMA2(acc2[i][j], qv[i].x, kv[j].x);
                    FMA2(acc2[i][j], qv[i].y, kv[j].y);
                }
        }
        const int kbase = ki * 64, qbase = qb * 64;
#pragma unroll
        for (int i = 0; i < 4; i++)
#pragma unroll
            for (int j = 0; j < 4; j++) {
                float s = hsum2(acc2[i][j]) * scale;
                SC[(q0 + i) * SC_STR + k0 + j] =
                    (kbase + k0 + j <= qbase + q0 + i) ? s : -1e9f;
            }
        __syncthreads();

        // ---- load V block (overwrite KVs; scores done reading) ----
#pragma unroll
        for (int i = 0; i < 8; i++) {
            int li = t + i * 256;
            int r = li >> 5, c = (li & 31) << 2;
            float4 a = *(const float4*)(g_qkv + (size_t)(ki * 64 + r) * QKV_W + 2560 + kvh * DH + c);
            *(float4*)&KVs[r * QS_STR + c] = a;
        }

        // ---- online softmax: 4 threads per row (register array, no aliasing) ----
        {
            int r = t >> 2, seg = (t & 3) << 4;
            float* row = &SC[r * SC_STR + seg];
            float rvv[16];
            *(float4*)(rvv)      = *(float4*)(row);
            *(float4*)(rvv + 4)  = *(float4*)(row + 4);
            *(float4*)(rvv + 8)  = *(float4*)(row + 8);
            *(float4*)(rvv + 12) = *(float4*)(row + 12);
            float m = rvv[0];
#pragma unroll
            for (int j = 1; j < 16; j++) m = fmaxf(m, rvv[j]);
            m = fmaxf(m, __shfl_xor_sync(0xFFFFFFFF, m, 1));
            m = fmaxf(m, __shfl_xor_sync(0xFFFFFFFF, m, 2));
            float mold = Mx[r];
            float mnew = fmaxf(mold, m);
            float al = __expf(mold - mnew);
            float rs = 0.f;
#pragma unroll
            for (int j = 0; j < 16; j++) {
                float p = __expf(rvv[j] - mnew);
                rvv[j] = p;
                rs += p;
            }
            *(float4*)(row)      = *(float4*)(rvv);
            *(float4*)(row + 4)  = *(float4*)(rvv + 4);
            *(float4*)(row + 8)  = *(float4*)(rvv + 8);
            *(float4*)(row + 12) = *(float4*)(rvv + 12);
            rs += __shfl_xor_sync(0xFFFFFFFF, rs, 1);
            rs += __shfl_xor_sync(0xFFFFFFFF, rs, 2);
            if ((t & 3) == 0) {
                Lw[r] = Lw[r] * al + rs;
                Mx[r] = mnew;
                Al[r] = al;
            }
        }
        __syncthreads();

        // ---- O accumulation: 4 queries x 8 dims, f32x2 over dims ----
        u64t alp[4];
#pragma unroll
        for (int i = 0; i < 4; i++) alp[i] = bcast2(Al[q0 + i]);
#pragma unroll
        for (int i = 0; i < 4; i++)
#pragma unroll
            for (int j = 0; j < 4; j++) MUL2(o2[i][j], o2[i][j], alp[i]);
        for (int c = 0; c < 64; c++) {
            ulonglong2 va = *(ulonglong2*)&KVs[c * QS_STR + dc];
            ulonglong2 vb = *(ulonglong2*)&KVs[c * QS_STR + dc + 4];
#pragma unroll
            for (int i = 0; i < 4; i++) {
                u64t pp = bcast2(SC[(q0 + i) * SC_STR + c]);
                FMA2(o2[i][0], pp, va.x);
                FMA2(o2[i][1], pp, va.y);
                FMA2(o2[i][2], pp, vb.x);
                FMA2(o2[i][3], pp, vb.y);
            }
        }
    }
    __syncthreads();

    // final: normalize, bf16 hi/lo split, vectorized store
#pragma unroll
    for (int i = 0; i < 4; i++) {
        float inv = 1.f / Lw[q0 + i];
        float vals[8];
#pragma unroll
        for (int jp = 0; jp < 4; jp++) unpack2(o2[i][jp], vals[2 * jp], vals[2 * jp + 1]);
        bf16 hh[8], ll[8];
#pragma unroll
        for (int j = 0; j < 8; j++) {
            float v = vals[j] * inv;
            hh[j] = __float2bfloat16(v);
            ll[j] = __float2bfloat16(v - __bfloat162float(hh[j]));
        }
        size_t ob = (size_t)(qb * 64 + q0 + i) * HID + h * DH + dc;
        *(uint4*)(g_bhi + ob) = *(uint4*)hh;
        *(uint4*)(g_blo + ob) = *(uint4*)ll;
    }
}

// ---------------- launch ----------------
extern "C" void kernel_launch(void* const* d_in, const int* in_sizes, int n_in,
                              void* d_out, int out_size) {
    const float* hid = (const float*)d_in[0];
    const int*   pos = (const int*)d_in[1];
    const float* Wq  = (const float*)d_in[2];
    const float* Wk  = (const float*)d_in[3];
    const float* Wv  = (const float*)d_in[4];
    const float* Wo  = (const float*)d_in[5];
    const float* H   = (const float*)d_in[6];
    float* out = (float*)d_out;

    float *qkvp, *sqp, *skp;
    bf16 *ahi, *alo, *bhi, *blo, *wqkvh, *wqkvl, *woh, *wol;
    cudaGetSymbolAddress((void**)&qkvp,  g_qkv);
    cudaGetSymbolAddress((void**)&sqp,   g_sq);
    cudaGetSymbolAddress((void**)&skp,   g_sk);
    cudaGetSymbolAddress((void**)&ahi,   g_ahi);
    cudaGetSymbolAddress((void**)&alo,   g_alo);
    cudaGetSymbolAddress((void**)&bhi,   g_bhi);
    cudaGetSymbolAddress((void**)&blo,   g_blo);
    cudaGetSymbolAddress((void**)&wqkvh, g_wqkv_h);
    cudaGetSymbolAddress((void**)&wqkvl, g_wqkv_l);
    cudaGetSymbolAddress((void**)&woh,   g_wot_h);
    cudaGetSymbolAddress((void**)&wol,   g_wot_l);

    cudaFuncSetAttribute(attn_kernel, cudaFuncAttributeMaxDynamicSharedMemorySize, ATTN_SMEM);
    cudaFuncSetAttribute(gemm_hmma, cudaFuncAttributeMaxDynamicSharedMemorySize, GH_SMEM);

    dim3 tb(32, 8);
    tsplit_qkv<<<dim3(QKV_W / 32, HID / 32), tb>>>(Wq, Wk, Wv, wqkvh, wqkvl);
    tsplit_kernel<<<dim3(HID / 32, HID / 32), tb>>>(Wo, woh, wol, HID, HID);
    split_kernel<<<(S_LEN * HID / 4 + 255) / 256, 256>>>(hid, ahi, alo, S_LEN * HID / 4);

    // fused QKV projection
    gemm_hmma<<<dim3(QKV_W / 128, S_LEN / 128), 256, GH_SMEM>>>(ahi, alo, wqkvh, wqkvl,
                                                                qkvp, S_LEN, QKV_W, HID);

    // RoPE
    cs_kernel<<<(S_LEN * 64 + 255) / 256, 256>>>(pos);
    rope_kernel<<<(S_LEN * NH * 64 + 255) / 256, 256>>>(0, NH);
    rope_kernel<<<(S_LEN * NKV * 64 + 255) / 256, 256>>>(2048, NKV);

    // sketches + top-k
    sketch_kernel<<<dim3(NBLK, NH), 128>>>(0, H, sqp);
    sketch_kernel<<<dim3(NBLK, NKV), 128>>>(2048, H, skp);
    topk_kernel<<<dim3(NBLK, NH), 64>>>();

    // block-sparse attention (f32x2, emits bf16 hi/lo)
    attn_kernel<<<dim3(NBLK, NH), 256, ATTN_SMEM>>>();

    // output projection
    gemm_hmma<<<dim3(HID / 128, S_LEN / 128), 256, GH_SMEM>>>(bhi, blo, woh, wol,
                                                              out, S_LEN, HID, HID);
}